// round 16
// baseline (speedup 1.0000x reference)
#include <cuda_runtime.h>
#include <cuda_bf16.h>
#include <cuda_fp16.h>
#include <cstdint>
#include <math.h>

#define N_NODES 50000
#define N_EDGES 640000
#define F 128
#define F4 32
#define NCLASS 40
#define SCAN_BLKS 49

// ---------------- scratch (static __device__, zero-initialized at load) ----------------
__device__ uint2         g_agghi[N_NODES * 32];  // aggregated sums, bf16 hi (4/uint2)
__device__ uint2         g_agglo[N_NODES * 32];  // aggregated sums, bf16 lo
__device__ __half        g_xh  [N_NODES * F];    // external x as fp16
__device__ __half        g_acth[N_NODES * F];    // activation table (fp16)
__device__ __nv_bfloat16 g_wthi[4 * F * F];
__device__ __nv_bfloat16 g_wtlo[4 * F * F];
__device__ int g_cnt[N_NODES];                   // ALWAYS zero at entry
__device__ int g_off[N_NODES + 1];
__device__ int g_cur[N_NODES];
__device__ int g_srcs[N_EDGES];
__device__ unsigned long long g_sstate[SCAN_BLKS];  // ALWAYS zero at entry

// ---------------- hist + W prep + x->fp16 convert (fused) ----------------
__global__ void hist_prep_kernel(const int* __restrict__ dst,
                                 const float* __restrict__ W1,
                                 const float* __restrict__ W2,
                                 const float* __restrict__ W3,
                                 const float* __restrict__ W4,
                                 const float4* __restrict__ X4) {
    int i = blockIdx.x * blockDim.x + threadIdx.x;
    if (i < N_EDGES) atomicAdd(&g_cnt[dst[i]], 1);
    int p = i - N_EDGES;
    if (p >= 0 && p < 4 * F * F) {
        int layer = p >> 14;
        int r = p & (F * F - 1);
        int k = r >> 7, n = r & 127;
        const float* W = (layer == 0) ? W1 : (layer == 1) ? W2 : (layer == 2) ? W3 : W4;
        float w = W[k * F + n];
        __nv_bfloat16 h = __float2bfloat16(w);
        g_wthi[layer * F * F + n * F + k] = h;
        g_wtlo[layer * F * F + n * F + k] = __float2bfloat16(w - __bfloat162float(h));
    }
    int q = i - N_EDGES - 4 * F * F;
    if (q >= 0 && q < N_NODES * F4) {
        float4 v = __ldg(&X4[q]);
        uint2 hv;
        *(__half2*)&hv.x = __floats2half2_rn(v.x, v.y);
        *(__half2*)&hv.y = __floats2half2_rn(v.z, v.w);
        ((uint2*)g_xh)[q] = hv;
    }
}

// ---------------- single-pass scan (decoupled lookback) ----------------
__global__ void scan_kernel() {
    __shared__ int sh[1024];
    __shared__ int sprefix;
    int tid = threadIdx.x;
    int bid = blockIdx.x;
    int i = bid * 1024 + tid;
    int v = (i < N_NODES) ? g_cnt[i] : 0;
    sh[tid] = v;
    __syncthreads();
    for (int off = 1; off < 1024; off <<= 1) {
        int t = (tid >= off) ? sh[tid - off] : 0;
        __syncthreads();
        sh[tid] += t;
        __syncthreads();
    }
    if (tid == 0) {
        int total = sh[1023];
        if (bid == 0) {
            atomicExch(&g_sstate[0], (2ULL << 32) | (unsigned)total);
            sprefix = 0;
        } else {
            atomicExch(&g_sstate[bid], (1ULL << 32) | (unsigned)total);
            int pref = 0;
            for (int j = bid - 1; j >= 0; ) {
                unsigned long long p;
                do { p = atomicAdd(&g_sstate[j], 0ULL); } while ((p >> 32) == 0);
                pref += (int)(p & 0xffffffffULL);
                if ((p >> 32) == 2) break;
                j--;
            }
            sprefix = pref;
            atomicExch(&g_sstate[bid], (2ULL << 32) | (unsigned)(pref + total));
        }
    }
    __syncthreads();
    int excl = sprefix + sh[tid] - v;
    if (i < N_NODES) { g_off[i] = excl; g_cur[i] = excl; }
    if (bid == 0 && tid == 0) g_off[N_NODES] = N_EDGES;
}

// ---------------- fill + restore zero-invariants ----------------
__global__ void fill_kernel(const int* __restrict__ src,
                            const int* __restrict__ dst) {
    int e = blockIdx.x * blockDim.x + threadIdx.x;
    if (e < N_EDGES) {
        int d = dst[e];
        int p = atomicAdd(&g_cur[d], 1);
        g_srcs[p] = src[e];
    }
    if (e < N_NODES) g_cnt[e] = 0;
    if (e < SCAN_BLKS) g_sstate[e] = 0;
}

// ---------------- aggregate (fp16 gather -> fp32 sum -> bf16 hi/lo store) ----------------
template<int SEL>
__global__ void agg_sum_kernel() {
    int node = (blockIdx.x * blockDim.x + threadIdx.x) >> 5;
    int lane = threadIdx.x & 31;
    if (node >= N_NODES) return;
    int s = g_off[node], e = g_off[node + 1];
    const uint2* tabh = (const uint2*)(SEL == 0 ? g_xh : g_acth);   // 32 uint2/row
    float4 acc = make_float4(0.f, 0.f, 0.f, 0.f);
    int i = s;
    for (; i + 7 < e; i += 8) {
        int u[8];
        #pragma unroll
        for (int j = 0; j < 8; j++) u[j] = __ldg(&g_srcs[i + j]);
        uint2 rv[8];
        #pragma unroll
        for (int j = 0; j < 8; j++) rv[j] = __ldg(&tabh[u[j] * 32 + lane]);
        #pragma unroll
        for (int j = 0; j < 8; j++) {
            float2 f0 = __half22float2(*(__half2*)&rv[j].x);
            float2 f1 = __half22float2(*(__half2*)&rv[j].y);
            acc.x += f0.x; acc.y += f0.y; acc.z += f1.x; acc.w += f1.y;
        }
    }
    for (; i < e; i++) {
        uint2 rv = __ldg(&tabh[__ldg(&g_srcs[i]) * 32 + lane]);
        float2 f0 = __half22float2(*(__half2*)&rv.x);
        float2 f1 = __half22float2(*(__half2*)&rv.y);
        acc.x += f0.x; acc.y += f0.y; acc.z += f1.x; acc.w += f1.y;
    }
    // split to bf16 hi/lo here (agg is latency-bound; GEMM is not)
    float vals[4] = {acc.x, acc.y, acc.z, acc.w};
    __nv_bfloat16 hi[4], lo[4];
    #pragma unroll
    for (int j = 0; j < 4; j++) {
        hi[j] = __float2bfloat16(vals[j]);
        lo[j] = __float2bfloat16(vals[j] - __bfloat162float(hi[j]));
    }
    int idx = node * 32 + lane;
    g_agghi[idx] = *(uint2*)hi;
    g_agglo[idx] = *(uint2*)lo;
}

// ---------------- GEMM + bias + L2norm + ReLU (+ fused head), pure-copy slabs ----------------
#define PT 40
#define GEMM_BASE (4 * 128 * PT * 2)
#define BS_OFF    GEMM_BASE
#define SS_OFF    (GEMM_BASE + 512)
#define SMEM_L    (GEMM_BASE + 512 + 1024)
#define XSH_PITCH 132
#define WSH_OFF   67584
#define BLSH_OFF  (WSH_OFF + 20480)
#define SMEM_L0   (BLSH_OFF + 160)

#define LDSM_X4(r0,r1,r2,r3,addr) \
    asm volatile("ldmatrix.sync.aligned.m8n8.x4.shared.b16 {%0,%1,%2,%3}, [%4];" \
        : "=r"(r0),"=r"(r1),"=r"(r2),"=r"(r3) : "r"(addr))
#define LDSM_X2(r0,r1,addr) \
    asm volatile("ldmatrix.sync.aligned.m8n8.x2.shared.b16 {%0,%1}, [%2];" \
        : "=r"(r0),"=r"(r1) : "r"(addr))
#define MMA16816(d,a0,a1,a2,a3,b0,b1) \
    asm volatile("mma.sync.aligned.m16n8k16.row.col.f32.bf16.bf16.f32 " \
        "{%0,%1,%2,%3},{%4,%5,%6,%7},{%8,%9},{%0,%1,%2,%3};" \
        : "+f"(d[0]),"+f"(d[1]),"+f"(d[2]),"+f"(d[3]) \
        : "r"(a0),"r"(a1),"r"(a2),"r"(a3),"r"(b0),"r"(b1))

__device__ __forceinline__ unsigned int smem_u32(const void* p) {
    return (unsigned int)__cvta_generic_to_shared(p);
}

template<int OUT>
__global__ __launch_bounds__(256, 2)
void gemm_norm_kernel(int layer, const float* __restrict__ bias,
                      float2* __restrict__ OUText, int nrows,
                      const float4* __restrict__ Wl4,
                      const float* __restrict__ bl,
                      float* __restrict__ logits,
                      float* __restrict__ probs) {
    extern __shared__ char smem_c[];
    __nv_bfloat16* xhi_s = (__nv_bfloat16*)smem_c;
    __nv_bfloat16* xlo_s = xhi_s + 128 * PT;
    __nv_bfloat16* whi_s = xlo_s + 128 * PT;
    __nv_bfloat16* wlo_s = whi_s + 128 * PT;
    float* b_s  = (float*)(smem_c + BS_OFF);
    float* ss_s = (float*)(smem_c + SS_OFF);

    const int tid  = threadIdx.x;
    const int lane = tid & 31;
    const int w    = tid >> 5;
    const int wr   = (w & 3) * 32;
    const int wc   = (w >> 2) * 64;
    const int row0 = blockIdx.x * 128;
    const int woff = layer * (F * F / 8);

    if (tid < 128) b_s[tid] = bias[tid];

    float acc[2][8][4];
    #pragma unroll
    for (int mt = 0; mt < 2; mt++)
        #pragma unroll
        for (int nt = 0; nt < 8; nt++)
            #pragma unroll
            for (int j = 0; j < 4; j++) acc[mt][nt][j] = 0.f;

    const int l15 = lane & 15;
    const int koA = (lane >> 4) << 3;
    const int koB = (l15 >> 3) << 3;

    // pure-copy slab pipeline: X hi/lo (pre-split by agg) + W hi/lo
    uint2 xh[4], xl[4];
    uint4 wv[4];
    auto load_slab = [&](int ks) {
        #pragma unroll
        for (int t = 0; t < 4; t++) {
            int i = tid + t * 256;
            int r = i >> 3, c = i & 7;
            int gr = row0 + r;
            if (gr < nrows) {
                int gidx = gr * 32 + ks * 8 + c;
                xh[t] = __ldg(&g_agghi[gidx]);
                xl[t] = __ldg(&g_agglo[gidx]);
            } else {
                xh[t] = make_uint2(0u, 0u);
                xl[t] = make_uint2(0u, 0u);
            }
        }
        #pragma unroll
        for (int t = 0; t < 4; t++) {
            int i = tid + t * 256;
            int whichW = i >> 9, r = (i >> 2) & 127, c = i & 3;
            int gidx = woff + r * 16 + ks * 4 + c;
            wv[t] = whichW ? ((const uint4*)g_wtlo)[gidx]
                           : ((const uint4*)g_wthi)[gidx];
        }
    };
    auto store_slab = [&]() {
        #pragma unroll
        for (int t = 0; t < 4; t++) {
            int i = tid + t * 256;
            int r = i >> 3, c = i & 7;
            int off = r * PT + c * 4;
            *(uint2*)(xhi_s + off) = xh[t];
            *(uint2*)(xlo_s + off) = xl[t];
        }
        #pragma unroll
        for (int t = 0; t < 4; t++) {
            int i = tid + t * 256;
            int whichW = i >> 9, r = (i >> 2) & 127, c = i & 3;
            __nv_bfloat16* base = whichW ? wlo_s : whi_s;
            *(uint4*)(base + r * PT + c * 8) = wv[t];
        }
    };

    load_slab(0);
    for (int ks = 0; ks < 4; ks++) {
        store_slab();
        __syncthreads();
        if (ks < 3) load_slab(ks + 1);

        #pragma unroll
        for (int j = 0; j < 2; j++) {
            unsigned int ahi[2][4], alo[2][4];
            #pragma unroll
            for (int mt = 0; mt < 2; mt++) {
                int r = wr + mt * 16 + l15;
                LDSM_X4(ahi[mt][0], ahi[mt][1], ahi[mt][2], ahi[mt][3],
                        smem_u32(xhi_s + r * PT + j * 16 + koA));
                LDSM_X4(alo[mt][0], alo[mt][1], alo[mt][2], alo[mt][3],
                        smem_u32(xlo_s + r * PT + j * 16 + koA));
            }
            #pragma unroll
            for (int nt = 0; nt < 8; nt++) {
                int boff = (wc + nt * 8 + (l15 & 7)) * PT + j * 16 + koB;
                unsigned int bh0, bh1, bl0, bl1;
                LDSM_X2(bh0, bh1, smem_u32(whi_s + boff));
                LDSM_X2(bl0, bl1, smem_u32(wlo_s + boff));
                #pragma unroll
                for (int mt = 0; mt < 2; mt++) {
                    MMA16816(acc[mt][nt], ahi[mt][0], ahi[mt][1], ahi[mt][2], ahi[mt][3], bh0, bh1);
                    MMA16816(acc[mt][nt], ahi[mt][0], ahi[mt][1], ahi[mt][2], ahi[mt][3], bl0, bl1);
                    MMA16816(acc[mt][nt], alo[mt][0], alo[mt][1], alo[mt][2], alo[mt][3], bh0, bh1);
                }
            }
        }
        __syncthreads();
    }

    // ---- epilogue: +bias, L2 norm ----
    const int rA = lane >> 2;
    const int cB = (lane & 3) * 2;
    float ssp[2][2];
    #pragma unroll
    for (int mt = 0; mt < 2; mt++) {
        ssp[mt][0] = 0.f; ssp[mt][1] = 0.f;
        #pragma unroll
        for (int nt = 0; nt < 8; nt++) {
            float b0 = b_s[wc + nt * 8 + cB];
            float b1 = b_s[wc + nt * 8 + cB + 1];
            acc[mt][nt][0] += b0; acc[mt][nt][1] += b1;
            acc[mt][nt][2] += b0; acc[mt][nt][3] += b1;
            ssp[mt][0] += acc[mt][nt][0] * acc[mt][nt][0] + acc[mt][nt][1] * acc[mt][nt][1];
            ssp[mt][1] += acc[mt][nt][2] * acc[mt][nt][2] + acc[mt][nt][3] * acc[mt][nt][3];
        }
        #pragma unroll
        for (int d = 1; d < 4; d <<= 1) {
            ssp[mt][0] += __shfl_xor_sync(0xFFFFFFFFu, ssp[mt][0], d);
            ssp[mt][1] += __shfl_xor_sync(0xFFFFFFFFu, ssp[mt][1], d);
        }
        if ((lane & 3) == 0) {
            ss_s[(wr + mt * 16 + rA) * 2 + (w >> 2)]     = ssp[mt][0];
            ss_s[(wr + mt * 16 + rA + 8) * 2 + (w >> 2)] = ssp[mt][1];
        }
    }
    __syncthreads();

    float invA[2], invB[2];
    #pragma unroll
    for (int mt = 0; mt < 2; mt++) {
        int r0l = wr + mt * 16 + rA;
        float ss0 = ss_s[r0l * 2] + ss_s[r0l * 2 + 1];
        float ss1 = ss_s[(r0l + 8) * 2] + ss_s[(r0l + 8) * 2 + 1];
        invA[mt] = 1.f / fmaxf(sqrtf(ss0), 1e-12f);
        invB[mt] = 1.f / fmaxf(sqrtf(ss1), 1e-12f);
    }
    __syncthreads();

    float* xsh = (float*)smem_c;
    #pragma unroll
    for (int mt = 0; mt < 2; mt++) {
        int r0l = wr + mt * 16 + rA;
        int gr = row0 + r0l;
        #pragma unroll
        for (int nt = 0; nt < 8; nt++) {
            int c = wc + nt * 8 + cB;
            float2 v0 = make_float2(fmaxf(acc[mt][nt][0] * invA[mt], 0.f),
                                    fmaxf(acc[mt][nt][1] * invA[mt], 0.f));
            float2 v1 = make_float2(fmaxf(acc[mt][nt][2] * invB[mt], 0.f),
                                    fmaxf(acc[mt][nt][3] * invB[mt], 0.f));
            if (OUT) {
                __half2* A2h = (__half2*)g_acth;
                if (gr < nrows)     A2h[gr * 64 + (c >> 1)]       = __floats2half2_rn(v0.x, v0.y);
                if (gr + 8 < nrows) A2h[(gr + 8) * 64 + (c >> 1)] = __floats2half2_rn(v1.x, v1.y);
            } else {
                if (gr < nrows)     OUText[gr * 64 + (c >> 1)]       = v0;
                if (gr + 8 < nrows) OUText[(gr + 8) * 64 + (c >> 1)] = v1;
                *(float2*)(xsh + r0l * XSH_PITCH + c)       = v0;
                *(float2*)(xsh + (r0l + 8) * XSH_PITCH + c) = v1;
            }
        }
    }

    if (OUT == 0) {
        float4* wsh4 = (float4*)(smem_c + WSH_OFF);
        float*  blsh = (float*)(smem_c + BLSH_OFF);
        for (int i = tid; i < 1280; i += 256) wsh4[i] = Wl4[i];
        if (tid < 40) blsh[tid] = bl[tid];
        __syncthreads();

        int node = tid >> 1;
        int half = tid & 1;
        int gn = row0 + node;

        float lg[20];
        #pragma unroll
        for (int j = 0; j < 20; j++) lg[j] = blsh[half * 20 + j];

        const float4* xrow = (const float4*)(xsh + node * XSH_PITCH);
        #pragma unroll 4
        for (int k4 = 0; k4 < 32; k4++) {
            float4 xvv = xrow[k4];
            float xs[4] = {xvv.x, xvv.y, xvv.z, xvv.w};
            #pragma unroll
            for (int kk = 0; kk < 4; kk++) {
                int k = k4 * 4 + kk;
                const float4* wrow = wsh4 + k * 10 + half * 5;
                #pragma unroll
                for (int c4 = 0; c4 < 5; c4++) {
                    float4 wvv = wrow[c4];
                    lg[c4 * 4 + 0] += xs[kk] * wvv.x;
                    lg[c4 * 4 + 1] += xs[kk] * wvv.y;
                    lg[c4 * 4 + 2] += xs[kk] * wvv.z;
                    lg[c4 * 4 + 3] += xs[kk] * wvv.w;
                }
            }
        }

        float m = -1e30f;
        #pragma unroll
        for (int j = 0; j < 20; j++) m = fmaxf(m, lg[j]);
        m = fmaxf(m, __shfl_xor_sync(0xFFFFFFFFu, m, 1));
        float sum = 0.f;
        float ex[20];
        #pragma unroll
        for (int j = 0; j < 20; j++) { ex[j] = expf(lg[j] - m); sum += ex[j]; }
        sum += __shfl_xor_sync(0xFFFFFFFFu, sum, 1);
        float inv = 1.f / sum;

        if (gn < nrows) {
            int base = gn * NCLASS + half * 20;
            #pragma unroll
            for (int j = 0; j < 20; j++) {
                logits[base + j] = lg[j];
                probs[base + j]  = ex[j] * inv;
            }
        }
    }
}

// ---------------- launch ----------------
extern "C" void kernel_launch(void* const* d_in, const int* in_sizes, int n_in,
                              void* d_out, int out_size) {
    const float* x  = (const float*)d_in[0];
    const int*   ei = (const int*)d_in[1];
    const float* W1 = (const float*)d_in[2];
    const float* b1 = (const float*)d_in[3];
    const float* W2 = (const float*)d_in[4];
    const float* b2 = (const float*)d_in[5];
    const float* W3 = (const float*)d_in[6];
    const float* b3 = (const float*)d_in[7];
    const float* W4 = (const float*)d_in[8];
    const float* b4 = (const float*)d_in[9];
    const float* Wl = (const float*)d_in[10];
    const float* bl = (const float*)d_in[11];

    const int* src = ei;
    const int* dst = ei + N_EDGES;

    float* out    = (float*)d_out;
    float* logits = out;
    float* probs  = out + N_NODES * NCLASS;
    float* x4out  = out + 2 * N_NODES * NCLASS;

    const int T = 256;
    const int gemm_blocks = (N_NODES + 127) / 128;
    const int agg_blocks  = (N_NODES * 32 + T - 1) / T;
    const int hp_blocks   = (N_EDGES + 4 * F * F + N_NODES * F4 + T - 1) / T;
    const int edge_blocks = (N_EDGES + T - 1) / T;

    cudaFuncSetAttribute(gemm_norm_kernel<1>, cudaFuncAttributeMaxDynamicSharedMemorySize, SMEM_L);
    cudaFuncSetAttribute(gemm_norm_kernel<0>, cudaFuncAttributeMaxDynamicSharedMemorySize, SMEM_L0);

    // CSR build + W prep + x->fp16 (one kernel)
    hist_prep_kernel<<<hp_blocks, T>>>(dst, W1, W2, W3, W4, (const float4*)x);
    scan_kernel<<<SCAN_BLKS, 1024>>>();
    fill_kernel<<<edge_blocks, T>>>(src, dst);

    // 4 layers (fp16 gathers, bf16-presplit GEMM handoff); layer 4 fuses head
    agg_sum_kernel<0><<<agg_blocks, T>>>();
    gemm_norm_kernel<1><<<gemm_blocks, T, SMEM_L>>>(0, b1, nullptr, N_NODES, nullptr, nullptr, nullptr, nullptr);
    agg_sum_kernel<1><<<agg_blocks, T>>>();
    gemm_norm_kernel<1><<<gemm_blocks, T, SMEM_L>>>(1, b2, nullptr, N_NODES, nullptr, nullptr, nullptr, nullptr);
    agg_sum_kernel<1><<<agg_blocks, T>>>();
    gemm_norm_kernel<1><<<gemm_blocks, T, SMEM_L>>>(2, b3, nullptr, N_NODES, nullptr, nullptr, nullptr, nullptr);
    agg_sum_kernel<1><<<agg_blocks, T>>>();
    gemm_norm_kernel<0><<<gemm_blocks, T, SMEM_L0>>>(3, b4, (float2*)x4out, N_NODES,
                                                     (const float4*)Wl, bl, logits, probs);
}